// round 1
// baseline (speedup 1.0000x reference)
#include <cuda_runtime.h>
#include <stdint.h>

// Problem shape (fixed by the reference): B=2, H=32, S_old=S_new=2048, D=128.
// Inputs (metadata order): k_cache, v_cache, k_new, v_new — each [2,32,2048,128] fp32.
// Output: k_full [2,32,4096,128] fp32 followed by v_full [2,32,4096,128] fp32.
//
// Math: per row of 128, scale = max(absmax/7, 1e-8); out = clip(rint(x/scale),-7,7)*scale.
// (int4 pack/unpack round-trip is the identity, concat is pure addressing.)

#define BH    64          // B*H
#define SOLD  2048
#define STOT  4096
#define DDIM  128
#define ROWS_PER_KV (BH * STOT)          // 262144
#define TOTAL_ROWS  (2 * ROWS_PER_KV)    // 524288 (k rows then v rows)

__global__ __launch_bounds__(256, 8)
void kv_int4_roundtrip_kernel(const float* __restrict__ k_cache,
                              const float* __restrict__ v_cache,
                              const float* __restrict__ k_new,
                              const float* __restrict__ v_new,
                              float* __restrict__ out)
{
    // one warp per output row
    const int warp_in_block = threadIdx.x >> 5;
    const int lane          = threadIdx.x & 31;
    const long long w = (long long)blockIdx.x * 8 + warp_in_block;   // global warp id = row id
    // grid sized exactly, no bounds check needed, but keep it cheap & safe:
    // (TOTAL_ROWS is divisible by 8 * gridDim granularity below)

    // Decode row -> source pointer
    const int kv  = (int)(w >> 18);            // / 262144
    const int r   = (int)(w & (ROWS_PER_KV - 1));
    const int bh  = r >> 12;                   // / 4096
    const int s   = r & (STOT - 1);            // % 4096
    const int s_in = s & (SOLD - 1);           // % 2048

    const float* src;
    if (kv == 0) src = (s < SOLD) ? k_cache : k_new;
    else         src = (s < SOLD) ? v_cache : v_new;

    const float4* src_row = (const float4*)(src + ((long long)bh * SOLD + s_in) * DDIM);
    float4*       dst_row = (float4*)(out + w * DDIM);

    // Load 4 floats per lane (512 B per warp, fully coalesced)
    float4 v = __ldg(src_row + lane);

    // absmax over the row
    float m = fmaxf(fmaxf(fabsf(v.x), fabsf(v.y)), fmaxf(fabsf(v.z), fabsf(v.w)));
    #pragma unroll
    for (int off = 16; off >= 1; off >>= 1)
        m = fmaxf(m, __shfl_xor_sync(0xffffffffu, m, off));

    // Two divisions per ROW (cheap), none per element.
    const float scale = fmaxf(m / 7.0f, 1e-8f);
    const float inv   = 1.0f / scale;

    float4 o;
    o.x = fminf(fmaxf(rintf(v.x * inv), -7.0f), 7.0f) * scale;
    o.y = fminf(fmaxf(rintf(v.y * inv), -7.0f), 7.0f) * scale;
    o.z = fminf(fmaxf(rintf(v.z * inv), -7.0f), 7.0f) * scale;
    o.w = fminf(fmaxf(rintf(v.w * inv), -7.0f), 7.0f) * scale;

    dst_row[lane] = o;
}

extern "C" void kernel_launch(void* const* d_in, const int* in_sizes, int n_in,
                              void* d_out, int out_size)
{
    const float* k_cache = (const float*)d_in[0];
    const float* v_cache = (const float*)d_in[1];
    const float* k_new   = (const float*)d_in[2];
    const float* v_new   = (const float*)d_in[3];
    float* out = (float*)d_out;

    // TOTAL_ROWS warps, 8 warps (256 threads) per block
    const int blocks = TOTAL_ROWS / 8;   // 65536
    kv_int4_roundtrip_kernel<<<blocks, 256>>>(k_cache, v_cache, k_new, v_new, out);
}

// round 3
// speedup vs baseline: 1.0951x; 1.0951x over previous
#include <cuda_runtime.h>
#include <stdint.h>

// Shape: B=2, H=32, S_old=S_new=2048, D=128.
// Inputs: k_cache, v_cache, k_new, v_new — each [64, 2048, 128] fp32 (BH flattened).
// Output: k_full [64,4096,128] then v_full [64,4096,128].
//
// Per row of 128: scale = max(absmax/7, 1e-8); out = clip(rint(x/scale),-7,7)*scale.
//
// 1-D grid of 16384 blocks; blocks [y*4096, (y+1)*4096) handle source y:
//   y = 0:k_cache 1:k_new 2:v_cache 3:v_new
// Each source region has 64*2048 = 131072 rows, read fully contiguously.
// Each warp handles 4 consecutive rows (one 2KB contiguous source block).

#define SOLD  2048
#define STOT  4096
#define DDIM  128
#define ROWS_PER_SRC (64 * SOLD)     // 131072
#define ROWS_PER_WARP 4
#define WARPS_PER_BLOCK 8
#define BLOCKS_PER_SRC (ROWS_PER_SRC / (ROWS_PER_WARP * WARPS_PER_BLOCK))  // 4096

__global__ __launch_bounds__(256)
void kv_int4_roundtrip_kernel(const float* __restrict__ k_cache,
                              const float* __restrict__ v_cache,
                              const float* __restrict__ k_new,
                              const float* __restrict__ v_new,
                              float* __restrict__ out)
{
    const int warp_in_block = threadIdx.x >> 5;
    const int lane          = threadIdx.x & 31;
    const int y             = blockIdx.x >> 12;          // source id, uniform per block
    const int bx            = blockIdx.x & (BLOCKS_PER_SRC - 1);

    // source select (uniform per block, no divergence)
    const float* src;
    switch (y) {
        case 0: src = k_cache; break;
        case 1: src = k_new;   break;
        case 2: src = v_cache; break;
        default: src = v_new;  break;
    }
    // output row base: v adds 64*4096 rows, "new" adds 2048 within each bh slab
    const int out_base_row = (y >> 1) * (64 * STOT) + (y & 1) * SOLD;

    // warp's first row within this source region
    const int w    = bx * WARPS_PER_BLOCK + warp_in_block;
    const int i0   = w * ROWS_PER_WARP;            // [0, 131072), multiple of 4
    const int bh   = i0 >> 11;                     // / 2048
    const int s_in = i0 & (SOLD - 1);              // % 2048 (4-row block never crosses)

    // contiguous 2KB source block = 128 float4s
    const float4* sp = (const float4*)(src + (long long)i0 * DDIM) + lane;
    const int out_row0 = out_base_row + bh * STOT + s_in;
    float4* dp = (float4*)(out + (long long)out_row0 * DDIM) + lane;

    // front-batched loads: 4 independent 512B-coalesced warp loads (MLP=4)
    float4 v0 = __ldcs(sp);
    float4 v1 = __ldcs(sp + 32);
    float4 v2 = __ldcs(sp + 64);
    float4 v3 = __ldcs(sp + 96);

    // 4 independent absmax reduction chains (pipelined shfls)
    float m0 = fmaxf(fmaxf(fabsf(v0.x), fabsf(v0.y)), fmaxf(fabsf(v0.z), fabsf(v0.w)));
    float m1 = fmaxf(fmaxf(fabsf(v1.x), fabsf(v1.y)), fmaxf(fabsf(v1.z), fabsf(v1.w)));
    float m2 = fmaxf(fmaxf(fabsf(v2.x), fabsf(v2.y)), fmaxf(fabsf(v2.z), fabsf(v2.w)));
    float m3 = fmaxf(fmaxf(fabsf(v3.x), fabsf(v3.y)), fmaxf(fabsf(v3.z), fabsf(v3.w)));
    #pragma unroll
    for (int off = 16; off >= 1; off >>= 1) {
        m0 = fmaxf(m0, __shfl_xor_sync(0xffffffffu, m0, off));
        m1 = fmaxf(m1, __shfl_xor_sync(0xffffffffu, m1, off));
        m2 = fmaxf(m2, __shfl_xor_sync(0xffffffffu, m2, off));
        m3 = fmaxf(m3, __shfl_xor_sync(0xffffffffu, m3, off));
    }

    const float s0 = fmaxf(m0 * (1.0f / 7.0f), 1e-8f);
    const float s1 = fmaxf(m1 * (1.0f / 7.0f), 1e-8f);
    const float s2 = fmaxf(m2 * (1.0f / 7.0f), 1e-8f);
    const float s3 = fmaxf(m3 * (1.0f / 7.0f), 1e-8f);
    const float r0 = 1.0f / s0;
    const float r1 = 1.0f / s1;
    const float r2 = 1.0f / s2;
    const float r3 = 1.0f / s3;

    float4 o0, o1, o2, o3;
    o0.x = fminf(fmaxf(rintf(v0.x * r0), -7.0f), 7.0f) * s0;
    o0.y = fminf(fmaxf(rintf(v0.y * r0), -7.0f), 7.0f) * s0;
    o0.z = fminf(fmaxf(rintf(v0.z * r0), -7.0f), 7.0f) * s0;
    o0.w = fminf(fmaxf(rintf(v0.w * r0), -7.0f), 7.0f) * s0;
    o1.x = fminf(fmaxf(rintf(v1.x * r1), -7.0f), 7.0f) * s1;
    o1.y = fminf(fmaxf(rintf(v1.y * r1), -7.0f), 7.0f) * s1;
    o1.z = fminf(fmaxf(rintf(v1.z * r1), -7.0f), 7.0f) * s1;
    o1.w = fminf(fmaxf(rintf(v1.w * r1), -7.0f), 7.0f) * s1;
    o2.x = fminf(fmaxf(rintf(v2.x * r2), -7.0f), 7.0f) * s2;
    o2.y = fminf(fmaxf(rintf(v2.y * r2), -7.0f), 7.0f) * s2;
    o2.z = fminf(fmaxf(rintf(v2.z * r2), -7.0f), 7.0f) * s2;
    o2.w = fminf(fmaxf(rintf(v2.w * r2), -7.0f), 7.0f) * s2;
    o3.x = fminf(fmaxf(rintf(v3.x * r3), -7.0f), 7.0f) * s3;
    o3.y = fminf(fmaxf(rintf(v3.y * r3), -7.0f), 7.0f) * s3;
    o3.z = fminf(fmaxf(rintf(v3.z * r3), -7.0f), 7.0f) * s3;
    o3.w = fminf(fmaxf(rintf(v3.w * r3), -7.0f), 7.0f) * s3;

    __stcs(dp,      o0);
    __stcs(dp + 32, o1);
    __stcs(dp + 64, o2);
    __stcs(dp + 96, o3);
}

extern "C" void kernel_launch(void* const* d_in, const int* in_sizes, int n_in,
                              void* d_out, int out_size)
{
    const float* k_cache = (const float*)d_in[0];
    const float* v_cache = (const float*)d_in[1];
    const float* k_new   = (const float*)d_in[2];
    const float* v_new   = (const float*)d_in[3];
    float* out = (float*)d_out;

    kv_int4_roundtrip_kernel<<<4 * BLOCKS_PER_SRC, 256>>>(k_cache, v_cache, k_new, v_new, out);
}